// round 12
// baseline (speedup 1.0000x reference)
#include <cuda_runtime.h>
#include <math.h>

#define NG 192
#define NTOT (NG * NG * NG)
#define BX 32
#define BY 4
#define BZ 4
#define TX (BX + 4)      // 36
#define TY (BY + 4)      // 8
#define TZ (BZ + 2)      // 6 : halo only on +z (forward offsets)
#define TILE (TX * TY * TZ)   // 1728

#define KN   500000.0f
#define MU   0.5f
#define EPSF 1e-4f
#define FULLMASK 0xffffffffu
#define BMASK 0x00FEFEFEu

#define CSHIFT 8                     // 256 voxels per coarse chunk
#define CNUM  (NTOT >> CSHIFT)       // 27648 coarse flags

// two-level hit flags; zero-initialized at load; fixup clears everything it
// set, so graph replays are deterministic. No dynamic allocation.
__device__ unsigned char g_flag[NTOT];    // fine: 1 byte per voxel
__device__ unsigned char g_cflag[CNUM];   // coarse: 1 byte per 256 voxels

__device__ __forceinline__ int wrapN(int v) {
    if (v < 0) v += NG;
    if (v >= NG) v -= NG;
    return v;
}

// exact per-voxel evaluation + store (pass B; idempotent per voxel)
__device__ __noinline__ void exact_voxel_store(
    int ga, int gb, int gc, float two_d, float eta,
    const float* __restrict__ xg, const float* __restrict__ yg,
    const float* __restrict__ zg, const float* __restrict__ vxg,
    const float* __restrict__ vyg, const float* __restrict__ vzg,
    float* __restrict__ out)
{
    const float two_d2 = two_d * two_d;
    const int gidx = (ga * NG + gb) * NG + gc;
    const float px = xg[gidx], py = yg[gidx], pz = zg[gidx];
    const float pvx = vxg[gidx], pvy = vyg[gidx], pvz = vzg[gidx];
    float fxc = 0.f, fyc = 0.f, fzc = 0.f;
    float fxd = 0.f, fyd = 0.f, fzd = 0.f;
    float frx = 0.f, fry = 0.f, frz = 0.f;
    #pragma unroll 1
    for (int oz = -2; oz <= 2; oz++) {
        const int na = wrapN(ga + oz);
        #pragma unroll 1
        for (int oy = -2; oy <= 2; oy++) {
            const int nb = wrapN(gb + oy);
            const int rowb = (na * NG + nb) * NG;
            #pragma unroll 1
            for (int ox = -2; ox <= 2; ox++) {
                const int nc = wrapN(gc + ox);
                const int nidx = rowb + nc;
                const float dx = px - xg[nidx];
                const float dy = py - yg[nidx];
                const float dz = pz - zg[nidx];
                const float d2 = fmaf(dz, dz, fmaf(dy, dy, dx * dx));
                // d2 == 0 (incl. self) contributes exactly 0 -> skip
                const bool hit = (d2 < two_d2) && (d2 > 0.0f);
                if (hit) {
                    const float dist = sqrtf(d2);
                    const float safe = fmaxf(EPSF, dist);
                    const float inv  = 1.0f / safe;
                    const float coef = KN * (dist - two_d) * inv;
                    fxc += coef * dx;
                    fyc += coef * dy;
                    fzc += coef * dz;
                    const float dvx = pvx - vxg[nidx];
                    const float dvy = pvy - vyg[nidx];
                    const float dvz = pvz - vzg[nidx];
                    const float vn  = (dvx * dx + dvy * dy + dvz * dz) * inv;
                    const float c2  = eta * vn * inv;
                    fxd += c2 * dx;
                    fyd += c2 * dy;
                    fzd += c2 * dz;
                }
            }
        }
    }
    // friction: only the LAST scan shift s=(2,2,2) survives, i.e. neighbor
    // offset (-2,-2,-2), evaluated against the fully accumulated sums.
    // NOTE: includes d2 == 0 overlaps (no d2 > 0 exclusion here).
    {
        const int na = wrapN(ga - 2);
        const int nb = wrapN(gb - 2);
        const int nc = wrapN(gc - 2);
        const int nidx = (na * NG + nb) * NG + nc;
        const float dx = px - xg[nidx];
        const float dy = py - yg[nidx];
        const float dz = pz - zg[nidx];
        const float d2 = fmaf(dz, dz, fmaf(dy, dy, dx * dx));
        if (d2 < two_d2) {
            const float dvx = pvx - vxg[nidx];
            const float dvy = pvy - vyg[nidx];
            const float dvz = pvz - vzg[nidx];
            frx = -(fabsf(fabsf(MU * fyc) + fabsf(MU * fzc) - MU * fxd)
                    * dvx / fmaxf(EPSF, fabsf(dvx)));
            fry = -(fabsf(fabsf(MU * fxc) + fabsf(MU * fzc) - MU * fyd)
                    * dvy / fmaxf(EPSF, fabsf(dvy)));
            // NB: reference uses diffvy in the z-friction numerator (kept).
            frz = -(fabsf(fabsf(MU * fxc) + fabsf(MU * fyc) - MU * fzd)
                    * dvy / fmaxf(EPSF, fabsf(dvz)));
        }
    }
    float* o = out + gidx;
    o[0 * NTOT] = fxc;
    o[1 * NTOT] = fyc;
    o[2 * NTOT] = fzc;
    o[3 * NTOT] = fxd;
    o[4 * NTOT] = fyd;
    o[5 * NTOT] = fzd;
    o[6 * NTOT] = frx;
    o[7 * NTOT] = fry;
    o[8 * NTOT] = frz;
}

// ---------------- Pass A: forward-only filter + zero-store + flagging -------
__global__ __launch_bounds__(BX * BY * BZ, 4)
void filter_kernel(const float* __restrict__ xg, const float* __restrict__ yg,
                   const float* __restrict__ zg,
                   const float* __restrict__ dptr, float* __restrict__ out)
{
    __shared__ unsigned qpk[TILE];   // bytes: (floor x, floor y, floor z, 0)

    const int lx = threadIdx.x, ly = threadIdx.y, lz = threadIdx.z;
    const int bx0 = blockIdx.x * BX;
    const int by0 = blockIdx.y * BY;
    const int bz0 = blockIdx.z * BZ;
    const int tid = (lz * BY + ly) * BX + lx;

    // halo key build: x,y wrap +-2; z only 0..+2 above (forward offsets)
    for (int idx = tid; idx < TILE; idx += BX * BY * BZ) {
        int tx = idx % TX;
        int r  = idx / TX;
        int ty = r % TY;
        int tz = r / TY;
        int gx = wrapN(bx0 + tx - 2);
        int gy = wrapN(by0 + ty - 2);
        int gz = wrapN(bz0 + tz);
        int g = (gz * NG + gy) * NG + gx;
        qpk[idx] = (unsigned)(int)xg[g] | ((unsigned)(int)yg[g] << 8)
                 | ((unsigned)(int)zg[g] << 16);
    }
    __syncthreads();

    const float d     = *dptr;
    const float two_d = 2.0f * d;
    // byte-filter validity: |dx| < two_d <= 1 => |floor diff| <= 1 per axis
    const bool filter_ok = (two_d <= 1.0f);

    const int cz = lz, cy = ly + 2, cx = lx + 2;   // own z at tile tz = lz
    const int cidx = (cz * TY + cy) * TX + cx;
    const unsigned pq = qpk[cidx];

    const int gz = bz0 + lz, gy = by0 + ly, gx = bx0 + lx;
    const int gidx = (gz * NG + gy) * NG + gx;

    // ---- byte prefilter over the 62 lexicographically-forward offsets ----
    bool need = !filter_ok;
    if (filter_ok) {
        unsigned m0 = ~0u, m1 = ~0u, m2 = ~0u, m3 = ~0u;
        int k = 0;
        #pragma unroll
        for (int oz = 0; oz <= 2; oz++) {
            #pragma unroll
            for (int oy = -2; oy <= 2; oy++) {
                if (oz == 0 && oy < 0) continue;
                #pragma unroll
                for (int ox = -2; ox <= 2; ox++) {
                    if (oz == 0 && oy == 0 && ox < 1) continue;
                    const unsigned nq = qpk[cidx + (oz * TY + oy) * TX + ox];
                    const unsigned v = __vabsdiffu4(pq, nq) & BMASK;
                    const int lane = (k++) & 3;
                    if (lane == 0)      m0 = min(m0, v);
                    else if (lane == 1) m1 = min(m1, v);
                    else if (lane == 2) m2 = min(m2, v);
                    else                m3 = min(m3, v);
                }
            }
        }
        need = (min(min(m0, m1), min(m2, m3)) == 0u);
    }

    // zero all nine outputs for every voxel; pass B overwrites true hits
    float* o = out + gidx;
    #pragma unroll
    for (int q = 0; q < 9; q++) o[q * NTOT] = 0.f;

    // rare (~0.8% of warps): exact forward check; flag BOTH pair endpoints
    // at both granularities (fine voxel byte + coarse chunk byte)
    if (__any_sync(FULLMASK, need)) {
        if (need) {
            const float two_d2 = two_d * two_d;
            const float px = xg[gidx], py = yg[gidx], pz = zg[gidx];
            #pragma unroll 1
            for (int oz = 0; oz <= 2; oz++) {
                #pragma unroll 1
                for (int oy = -2; oy <= 2; oy++) {
                    if (oz == 0 && oy < 0) continue;
                    #pragma unroll 1
                    for (int ox = -2; ox <= 2; ox++) {
                        if (oz == 0 && oy == 0 && ox < 1) continue;
                        const int nidx = (wrapN(gz + oz) * NG + wrapN(gy + oy)) * NG
                                       + wrapN(gx + ox);
                        const float dx = px - xg[nidx];
                        const float dy = py - yg[nidx];
                        const float dz = pz - zg[nidx];
                        const float d2 = fmaf(dz, dz, fmaf(dy, dy, dx * dx));
                        // include d2 == 0: friction needs zero-distance overlaps
                        if (d2 < two_d2) {
                            g_flag[gidx] = 1;
                            g_flag[nidx] = 1;
                            g_cflag[gidx >> CSHIFT] = 1;
                            g_cflag[nidx >> CSHIFT] = 1;
                        }
                    }
                }
            }
        }
    }
}

// ---------------- Pass B: coarse scan -> fine scan -> evaluate + clear ------
#define FBLK 256
#define FTHREADS (CNUM / 16)          // 1728 threads, one uint4 of coarse each
__global__ __launch_bounds__(FBLK)
void fixup_kernel(const float* __restrict__ xg, const float* __restrict__ yg,
                  const float* __restrict__ zg, const float* __restrict__ vxg,
                  const float* __restrict__ vyg, const float* __restrict__ vzg,
                  const float* __restrict__ dptr, float* __restrict__ out,
                  float eta)
{
    const int t = blockIdx.x * FBLK + threadIdx.x;
    if (t >= FTHREADS) return;
    uint4 cf = ((const uint4*)g_cflag)[t];
    if (!(cf.x | cf.y | cf.z | cf.w)) return;       // common: nothing here

    const float two_d = 2.0f * (*dptr);
    #pragma unroll 1
    for (int c = 0; c < 16; c++) {
        const unsigned w = (c < 4) ? cf.x : (c < 8) ? cf.y : (c < 12) ? cf.z : cf.w;
        if (!((w >> (8 * (c & 3))) & 0xFFu)) continue;
        // fine chunk fc covers voxels [fc*256, fc*256+256)
        const int fc = t * 16 + c;
        uint4* fine = (uint4*)(g_flag + (fc << CSHIFT));
        #pragma unroll 1
        for (int q = 0; q < 16; q++) {              // 16 x 16 bytes = 256
            uint4 f = fine[q];
            if (f.x | f.y | f.z | f.w) {
                const int vbase = (fc << CSHIFT) + q * 16;
                #pragma unroll 1
                for (int b = 0; b < 16; b++) {
                    const unsigned fw = (b < 4) ? f.x : (b < 8) ? f.y
                                      : (b < 12) ? f.z : f.w;
                    if ((fw >> (8 * (b & 3))) & 0xFFu) {
                        const int v = vbase + b;
                        const int gx = v % NG;
                        const int r  = v / NG;
                        exact_voxel_store(r / NG, r % NG, gx, two_d, eta,
                                          xg, yg, zg, vxg, vyg, vzg, out);
                    }
                }
                fine[q] = make_uint4(0, 0, 0, 0);   // clear fine flags
            }
        }
    }
    ((uint4*)g_cflag)[t] = make_uint4(0, 0, 0, 0);  // clear coarse flags
}

extern "C" void kernel_launch(void* const* d_in, const int* in_sizes, int n_in,
                              void* d_out, int out_size)
{
    const float* xg   = (const float*)d_in[0];
    const float* yg   = (const float*)d_in[1];
    const float* zg   = (const float*)d_in[2];
    const float* vxg  = (const float*)d_in[3];
    const float* vyg  = (const float*)d_in[4];
    const float* vzg  = (const float*)d_in[5];
    const float* dptr = (const float*)d_in[6];
    float* out = (float*)d_out;

    // ETA = 2*gamma*sqrt(KN), gamma = alpha/sqrt(alpha^2+1), alpha = -ln(0.7)/pi
    const double alpha = -log(0.7) / M_PI;
    const double gam   = alpha / sqrt(alpha * alpha + 1.0);
    const float  eta   = (float)(2.0 * gam * sqrt(500000.0));

    dim3 blockA(BX, BY, BZ);
    dim3 gridA(NG / BX, NG / BY, NG / BZ);
    filter_kernel<<<gridA, blockA>>>(xg, yg, zg, dptr, out);

    fixup_kernel<<<(FTHREADS + FBLK - 1) / FBLK, FBLK>>>(
        xg, yg, zg, vxg, vyg, vzg, dptr, out, eta);
}

// round 13
// speedup vs baseline: 3.9518x; 3.9518x over previous
#include <cuda_runtime.h>
#include <math.h>

#define NG 192
#define NTOT (NG * NG * NG)
#define BX 32
#define BY 4
#define BZ 4
#define TX (BX + 4)      // 36
#define TY (BY + 4)      // 8
#define TZ (BZ + 2)      // 6 : halo only on +z (forward offsets)
#define TILE (TX * TY * TZ)   // 1728

#define KN   500000.0f
#define MU   0.5f
#define EPSF 1e-4f
#define FULLMASK 0xffffffffu
#define BMASK 0x00FEFEFEu
#define LCAP (1 << 20)   // hit-list capacity; ~500 expected

// hit list + counter; statically zero; trailing reset kernel restores the
// zero invariant each run, so graph replays are deterministic.
__device__ int g_count;
__device__ int g_list[LCAP];

__device__ __forceinline__ int wrapN(int v) {
    if (v < 0) v += NG;
    if (v >= NG) v -= NG;
    return v;
}

// ---------------- Pass A: forward-only filter + zero-store + list append ----
__global__ __launch_bounds__(BX * BY * BZ, 4)
void filter_kernel(const float* __restrict__ xg, const float* __restrict__ yg,
                   const float* __restrict__ zg,
                   const float* __restrict__ dptr, float* __restrict__ out)
{
    __shared__ unsigned qpk[TILE];   // bytes: (floor x, floor y, floor z, 0)

    const int lx = threadIdx.x, ly = threadIdx.y, lz = threadIdx.z;
    const int bx0 = blockIdx.x * BX;
    const int by0 = blockIdx.y * BY;
    const int bz0 = blockIdx.z * BZ;
    const int tid = (lz * BY + ly) * BX + lx;

    // halo key build: x,y wrap +-2; z only 0..+2 above (forward offsets)
    for (int idx = tid; idx < TILE; idx += BX * BY * BZ) {
        int tx = idx % TX;
        int r  = idx / TX;
        int ty = r % TY;
        int tz = r / TY;
        int gx = wrapN(bx0 + tx - 2);
        int gy = wrapN(by0 + ty - 2);
        int gz = wrapN(bz0 + tz);
        int g = (gz * NG + gy) * NG + gx;
        qpk[idx] = (unsigned)(int)xg[g] | ((unsigned)(int)yg[g] << 8)
                 | ((unsigned)(int)zg[g] << 16);
    }
    __syncthreads();

    const float d     = *dptr;
    const float two_d = 2.0f * d;
    // byte-filter validity: |dx| < two_d <= 1 => |floor diff| <= 1 per axis
    const bool filter_ok = (two_d <= 1.0f);

    const int cz = lz, cy = ly + 2, cx = lx + 2;   // own z at tile tz = lz
    const int cidx = (cz * TY + cy) * TX + cx;
    const unsigned pq = qpk[cidx];

    const int gz = bz0 + lz, gy = by0 + ly, gx = bx0 + lx;
    const int gidx = (gz * NG + gy) * NG + gx;

    // ---- byte prefilter over the 62 lexicographically-forward offsets ----
    bool need = !filter_ok;
    if (filter_ok) {
        unsigned m0 = ~0u, m1 = ~0u, m2 = ~0u, m3 = ~0u;
        int k = 0;
        #pragma unroll
        for (int oz = 0; oz <= 2; oz++) {
            #pragma unroll
            for (int oy = -2; oy <= 2; oy++) {
                if (oz == 0 && oy < 0) continue;
                #pragma unroll
                for (int ox = -2; ox <= 2; ox++) {
                    if (oz == 0 && oy == 0 && ox < 1) continue;
                    const unsigned nq = qpk[cidx + (oz * TY + oy) * TX + ox];
                    const unsigned v = __vabsdiffu4(pq, nq) & BMASK;
                    const int lane = (k++) & 3;
                    if (lane == 0)      m0 = min(m0, v);
                    else if (lane == 1) m1 = min(m1, v);
                    else if (lane == 2) m2 = min(m2, v);
                    else                m3 = min(m3, v);
                }
            }
        }
        need = (min(min(m0, m1), min(m2, m3)) == 0u);
    }

    // zero all nine outputs for every voxel; pass B overwrites true hits
    float* o = out + gidx;
    #pragma unroll
    for (int q = 0; q < 9; q++) o[q * NTOT] = 0.f;

    // rare (~0.8% of warps): exact forward check; append BOTH pair endpoints
    if (__any_sync(FULLMASK, need)) {
        if (need) {
            const float two_d2 = two_d * two_d;
            const float px = xg[gidx], py = yg[gidx], pz = zg[gidx];
            #pragma unroll 1
            for (int oz = 0; oz <= 2; oz++) {
                #pragma unroll 1
                for (int oy = -2; oy <= 2; oy++) {
                    if (oz == 0 && oy < 0) continue;
                    #pragma unroll 1
                    for (int ox = -2; ox <= 2; ox++) {
                        if (oz == 0 && oy == 0 && ox < 1) continue;
                        const int nidx = (wrapN(gz + oz) * NG + wrapN(gy + oy)) * NG
                                       + wrapN(gx + ox);
                        const float dx = px - xg[nidx];
                        const float dy = py - yg[nidx];
                        const float dz = pz - zg[nidx];
                        const float d2 = fmaf(dz, dz, fmaf(dy, dy, dx * dx));
                        // include d2 == 0: friction needs zero-distance overlaps
                        if (d2 < two_d2) {
                            int i0 = atomicAdd(&g_count, 2);
                            if (i0 + 1 < LCAP) {
                                g_list[i0]     = gidx;
                                g_list[i0 + 1] = nidx;
                            }
                        }
                    }
                }
            }
        }
    }
}

// ---------------- Pass B: WARP-per-voxel exact evaluation -------------------
#define FBLK 256
#define FGRD 128
__global__ __launch_bounds__(FBLK)
void fixup_kernel(const float* __restrict__ xg, const float* __restrict__ yg,
                  const float* __restrict__ zg, const float* __restrict__ vxg,
                  const float* __restrict__ vyg, const float* __restrict__ vzg,
                  const float* __restrict__ dptr, float* __restrict__ out,
                  float eta)
{
    const int n = min(g_count, LCAP);
    if (n == 0) return;
    const int lane  = threadIdx.x & 31;
    const int warp  = (blockIdx.x * FBLK + threadIdx.x) >> 5;
    const int nwarp = (FGRD * FBLK) >> 5;
    const float two_d  = 2.0f * (*dptr);
    const float two_d2 = two_d * two_d;

    for (int i = warp; i < n; i += nwarp) {
        const int v  = g_list[i];
        const int gx = v % NG;
        const int r  = v / NG;
        const int gy = r % NG;
        const int gz = r / NG;

        // all lanes load the (L1-broadcast) center values
        const float px = xg[v], py = yg[v], pz = zg[v];
        const float pvx = vxg[v], pvy = vyg[v], pvz = vzg[v];

        float fxc = 0.f, fyc = 0.f, fzc = 0.f;
        float fxd = 0.f, fyd = 0.f, fzd = 0.f;

        // lane l handles offsets l, l+32, l+64, l+96 of the 125 (self is
        // k = 62, excluded by the d2 > 0 guard). Independent loads -> MLP.
        #pragma unroll
        for (int kk = 0; kk < 4; kk++) {
            const int k = lane + 32 * kk;
            if (k < 125) {
                const int oz = k / 25 - 2;
                const int oy = (k / 5) % 5 - 2;
                const int ox = k % 5 - 2;
                const int nidx = (wrapN(gz + oz) * NG + wrapN(gy + oy)) * NG
                               + wrapN(gx + ox);
                const float dx = px - xg[nidx];
                const float dy = py - yg[nidx];
                const float dz = pz - zg[nidx];
                const float d2 = fmaf(dz, dz, fmaf(dy, dy, dx * dx));
                // d2 == 0 (incl. self) contributes exactly 0 -> skip
                if (d2 < two_d2 && d2 > 0.0f) {
                    const float dist = sqrtf(d2);
                    const float safe = fmaxf(EPSF, dist);
                    const float inv  = 1.0f / safe;
                    const float coef = KN * (dist - two_d) * inv;
                    fxc += coef * dx;
                    fyc += coef * dy;
                    fzc += coef * dz;
                    const float dvx = pvx - vxg[nidx];
                    const float dvy = pvy - vyg[nidx];
                    const float dvz = pvz - vzg[nidx];
                    const float vn  = (dvx * dx + dvy * dy + dvz * dz) * inv;
                    const float c2  = eta * vn * inv;
                    fxd += c2 * dx;
                    fyd += c2 * dy;
                    fzd += c2 * dz;
                }
            }
        }

        // warp-reduce the six accumulators
        #pragma unroll
        for (int s = 16; s > 0; s >>= 1) {
            fxc += __shfl_xor_sync(FULLMASK, fxc, s);
            fyc += __shfl_xor_sync(FULLMASK, fyc, s);
            fzc += __shfl_xor_sync(FULLMASK, fzc, s);
            fxd += __shfl_xor_sync(FULLMASK, fxd, s);
            fyd += __shfl_xor_sync(FULLMASK, fyd, s);
            fzd += __shfl_xor_sync(FULLMASK, fzd, s);
        }

        if (lane == 0) {
            // friction: only the LAST scan shift s=(2,2,2) survives, i.e.
            // neighbor offset (-2,-2,-2), against the fully accumulated sums.
            // Includes d2 == 0 overlaps (no d2 > 0 exclusion here).
            float frx = 0.f, fry = 0.f, frz = 0.f;
            const int nidx = (wrapN(gz - 2) * NG + wrapN(gy - 2)) * NG
                           + wrapN(gx - 2);
            const float dx = px - xg[nidx];
            const float dy = py - yg[nidx];
            const float dz = pz - zg[nidx];
            const float d2 = fmaf(dz, dz, fmaf(dy, dy, dx * dx));
            if (d2 < two_d2) {
                const float dvx = pvx - vxg[nidx];
                const float dvy = pvy - vyg[nidx];
                const float dvz = pvz - vzg[nidx];
                frx = -(fabsf(fabsf(MU * fyc) + fabsf(MU * fzc) - MU * fxd)
                        * dvx / fmaxf(EPSF, fabsf(dvx)));
                fry = -(fabsf(fabsf(MU * fxc) + fabsf(MU * fzc) - MU * fyd)
                        * dvy / fmaxf(EPSF, fabsf(dvy)));
                // NB: reference uses diffvy in the z-friction numerator (kept).
                frz = -(fabsf(fabsf(MU * fxc) + fabsf(MU * fyc) - MU * fzd)
                        * dvy / fmaxf(EPSF, fabsf(dvz)));
            }
            float* o = out + v;
            o[0 * NTOT] = fxc;
            o[1 * NTOT] = fyc;
            o[2 * NTOT] = fzc;
            o[3 * NTOT] = fxd;
            o[4 * NTOT] = fyd;
            o[5 * NTOT] = fzd;
            o[6 * NTOT] = frx;
            o[7 * NTOT] = fry;
            o[8 * NTOT] = frz;
        }
    }
}

// ---------------- Pass C: restore counter invariant for graph replay --------
__global__ void reset_kernel() {
    g_count = 0;
}

extern "C" void kernel_launch(void* const* d_in, const int* in_sizes, int n_in,
                              void* d_out, int out_size)
{
    const float* xg   = (const float*)d_in[0];
    const float* yg   = (const float*)d_in[1];
    const float* zg   = (const float*)d_in[2];
    const float* vxg  = (const float*)d_in[3];
    const float* vyg  = (const float*)d_in[4];
    const float* vzg  = (const float*)d_in[5];
    const float* dptr = (const float*)d_in[6];
    float* out = (float*)d_out;

    // ETA = 2*gamma*sqrt(KN), gamma = alpha/sqrt(alpha^2+1), alpha = -ln(0.7)/pi
    const double alpha = -log(0.7) / M_PI;
    const double gam   = alpha / sqrt(alpha * alpha + 1.0);
    const float  eta   = (float)(2.0 * gam * sqrt(500000.0));

    dim3 blockA(BX, BY, BZ);
    dim3 gridA(NG / BX, NG / BY, NG / BZ);
    filter_kernel<<<gridA, blockA>>>(xg, yg, zg, dptr, out);

    fixup_kernel<<<FGRD, FBLK>>>(xg, yg, zg, vxg, vyg, vzg, dptr, out, eta);

    reset_kernel<<<1, 1>>>();   // runs after fixup reads g_count
}